// round 1
// baseline (speedup 1.0000x reference)
#include <cuda_runtime.h>
#include <math.h>
#include <stdint.h>

// ---------------------------------------------------------------------------
// ProteinFeatures: per-edge features
//   E row (39) = [cos(8), sin(8), RBF(16), dU(3), Q(4)]
// Outputs concatenated as float32:
//   [ E (Eg*39) | edge_index (2*Eg) | edge_length (Eg) |
//     new_edge_index (2*nr) | E_new (nr*39) ]
// ---------------------------------------------------------------------------

#define NMAX 210000

__device__ float g_Xca[NMAX * 3];
__device__ float g_O[NMAX * 9];

__device__ __forceinline__ float3 f3sub(float3 a, float3 b) {
    return make_float3(a.x - b.x, a.y - b.y, a.z - b.z);
}
__device__ __forceinline__ float3 f3cross(float3 a, float3 b) {
    return make_float3(a.y * b.z - a.z * b.y,
                       a.z * b.x - a.x * b.z,
                       a.x * b.y - a.y * b.x);
}
__device__ __forceinline__ float f3dot(float3 a, float3 b) {
    return a.x * b.x + a.y * b.y + a.z * b.z;
}
__device__ __forceinline__ float3 f3norm(float3 a) {
    float n = sqrtf(f3dot(a, a));
    float inv = 1.0f / fmaxf(n, 1e-12f);
    return make_float3(a.x * inv, a.y * inv, a.z * inv);
}
__device__ __forceinline__ float fsgn(float v) {
    return (float)((v > 0.0f) - (v < 0.0f));
}

// freq_k = 10000^(-2k/16) = 10^(-k/2)
__constant__ float c_freq[8] = {
    1.0f, 0.31622776601683794f, 0.1f, 0.03162277660168379f,
    0.01f, 0.0031622776601683794f, 0.001f, 0.00031622776601683794f
};

// ---------------------------------------------------------------------------
// Kernel 1: extract contiguous X_ca and build per-node orientation frames O[i]
// ---------------------------------------------------------------------------
__global__ void prep_kernel(const float* __restrict__ X, int N) {
    int i = blockIdx.x * blockDim.x + threadIdx.x;
    if (i >= N) return;

    // CA atom is atom index 1 of 4: X[i*12 + 3..5]
    float3 xc = make_float3(X[i * 12 + 3], X[i * 12 + 4], X[i * 12 + 5]);
    g_Xca[i * 3 + 0] = xc.x;
    g_Xca[i * 3 + 1] = xc.y;
    g_Xca[i * 3 + 2] = xc.z;

    float* Orow = g_O + (size_t)i * 9;
    if (i == 0 || i == N - 1) {
#pragma unroll
        for (int j = 0; j < 9; j++) Orow[j] = 0.0f;
        return;
    }
    float3 xm = make_float3(X[(i - 1) * 12 + 3], X[(i - 1) * 12 + 4], X[(i - 1) * 12 + 5]);
    float3 xp = make_float3(X[(i + 1) * 12 + 3], X[(i + 1) * 12 + 4], X[(i + 1) * 12 + 5]);

    float3 u2 = f3norm(f3sub(xc, xm));   // U[i-1]
    float3 u1 = f3norm(f3sub(xp, xc));   // U[i]
    float3 n2 = f3norm(f3cross(u2, u1));
    float3 o1 = f3norm(f3sub(u2, u1));
    float3 r2 = f3cross(o1, n2);

    Orow[0] = o1.x; Orow[1] = o1.y; Orow[2] = o1.z;
    Orow[3] = n2.x; Orow[4] = n2.y; Orow[5] = n2.z;
    Orow[6] = r2.x; Orow[7] = r2.y; Orow[8] = r2.z;
}

// ---------------------------------------------------------------------------
// Kernel 2: per-edge features
// ---------------------------------------------------------------------------
__global__ void edge_kernel(const int* __restrict__ ei,
                            const int* __restrict__ S_id,
                            float* __restrict__ out,
                            int E) {
    int e = blockIdx.x * blockDim.x + threadIdx.x;
    if (e >= E) return;

    int r = ei[e];
    int c = ei[E + e];

    float3 xr = make_float3(g_Xca[r * 3 + 0], g_Xca[r * 3 + 1], g_Xca[r * 3 + 2]);
    float3 xc = make_float3(g_Xca[c * 3 + 0], g_Xca[c * 3 + 1], g_Xca[c * 3 + 2]);

    float3 dXe = f3sub(xc, xr);                 // X_ca[c] - X_ca[r]
    float d = sqrtf(f3dot(dXe, dXe));           // edge length (symmetric)

    float* Erow = out + (size_t)e * 39;

    // positional encodings: cols 0..7 cos, 8..15 sin
    float eidx = (float)(S_id[c] - S_id[r]);
#pragma unroll
    for (int k = 0; k < 8; k++) {
        float a = eidx * c_freq[k];
        Erow[k]     = cosf(a);
        Erow[8 + k] = sinf(a);
    }

    // RBF: cols 16..31; mu_j = j*20/15, sigma = 1.25
#pragma unroll
    for (int j = 0; j < 16; j++) {
        float t = (d - (float)j * (20.0f / 15.0f)) * 0.8f;
        Erow[16 + j] = expf(-t * t);
    }

    // orientation features
    float Or[9], Oc[9];
    const float* po = g_O + (size_t)r * 9;
    const float* pc = g_O + (size_t)c * 9;
#pragma unroll
    for (int j = 0; j < 9; j++) { Or[j] = po[j]; Oc[j] = pc[j]; }

    // dU = l2norm(O[c] @ dXe)
    float du0 = Oc[0] * dXe.x + Oc[1] * dXe.y + Oc[2] * dXe.z;
    float du1 = Oc[3] * dXe.x + Oc[4] * dXe.y + Oc[5] * dXe.z;
    float du2 = Oc[6] * dXe.x + Oc[7] * dXe.y + Oc[8] * dXe.z;
    {
        float n = sqrtf(du0 * du0 + du1 * du1 + du2 * du2);
        float inv = 1.0f / fmaxf(n, 1e-12f);
        Erow[32] = du0 * inv; Erow[33] = du1 * inv; Erow[34] = du2 * inv;
    }

    // R = O[r] @ O[c]^T : R[i][k] = dot(Or row i, Oc row k)
    float R[3][3];
#pragma unroll
    for (int i = 0; i < 3; i++) {
#pragma unroll
        for (int k = 0; k < 3; k++) {
            R[i][k] = Or[3 * i + 0] * Oc[3 * k + 0]
                    + Or[3 * i + 1] * Oc[3 * k + 1]
                    + Or[3 * i + 2] * Oc[3 * k + 2];
        }
    }

    float Rxx = R[0][0], Ryy = R[1][1], Rzz = R[2][2];
    float m0 = 0.5f * sqrtf(fabsf(1.0f + Rxx - Ryy - Rzz));
    float m1 = 0.5f * sqrtf(fabsf(1.0f - Rxx + Ryy - Rzz));
    float m2 = 0.5f * sqrtf(fabsf(1.0f - Rxx - Ryy + Rzz));
    float qx = fsgn(R[2][1] - R[1][2]) * m0;
    float qy = fsgn(R[0][2] - R[2][0]) * m1;
    float qz = fsgn(R[1][0] - R[0][1]) * m2;
    float qw = 0.5f * sqrtf(fmaxf(1.0f + Rxx + Ryy + Rzz, 0.0f));
    {
        float n = sqrtf(qx * qx + qy * qy + qz * qz + qw * qw);
        float inv = 1.0f / fmaxf(n, 1e-12f);
        Erow[35] = qx * inv; Erow[36] = qy * inv; Erow[37] = qz * inv; Erow[38] = qw * inv;
    }

    // edge_index passthrough (as float) and edge_length
    size_t offEI = (size_t)39 * E;
    size_t offEL = (size_t)41 * E;
    out[offEI + e]     = (float)r;
    out[offEI + E + e] = (float)c;
    out[offEL + e]     = d;
}

// ---------------------------------------------------------------------------
// Kernel 3: new (ligand) edges
// ---------------------------------------------------------------------------
__global__ void new_edge_kernel(const int* __restrict__ row_new,
                                const int* __restrict__ col_new,
                                const float* __restrict__ pos,
                                float* __restrict__ out,
                                int E, int nr, int N) {
    int t = blockIdx.x * blockDim.x + threadIdx.x;
    if (t >= nr) return;

    int rn = row_new[t];
    int cn = col_new[t];

    float dx = g_Xca[rn * 3 + 0] - pos[cn * 3 + 0];
    float dy = g_Xca[rn * 3 + 1] - pos[cn * 3 + 1];
    float dz = g_Xca[rn * 3 + 2] - pos[cn * 3 + 2];
    float d = sqrtf(dx * dx + dy * dy + dz * dz);

    size_t offNEI = (size_t)42 * E;
    size_t offEN  = offNEI + (size_t)2 * nr;

    out[offNEI + t]      = (float)rn;
    out[offNEI + nr + t] = (float)(cn + N);

    float* Erow = out + offEN + (size_t)t * 39;
#pragma unroll
    for (int k = 0; k < 16; k++) Erow[k] = 0.0f;
#pragma unroll
    for (int j = 0; j < 16; j++) {
        float u = (d - (float)j * (20.0f / 15.0f)) * 0.8f;
        Erow[16 + j] = expf(-u * u);
    }
#pragma unroll
    for (int k = 32; k < 39; k++) Erow[k] = 0.0f;
}

// ---------------------------------------------------------------------------
extern "C" void kernel_launch(void* const* d_in, const int* in_sizes, int n_in,
                              void* d_out, int out_size) {
    const float* X       = (const float*)d_in[0];
    const float* pos     = (const float*)d_in[1];
    const int*   ei      = (const int*)d_in[2];
    const int*   S_id    = (const int*)d_in[3];
    // d_in[4] = batch (unused: col_new already holds batch[row_new])
    const int*   row_new = (const int*)d_in[5];
    const int*   col_new = (const int*)d_in[6];

    int N  = in_sizes[0] / 12;
    int E  = in_sizes[2] / 2;
    int nr = in_sizes[5];

    float* out = (float*)d_out;

    prep_kernel<<<(N + 255) / 256, 256>>>(X, N);
    edge_kernel<<<(E + 127) / 128, 128>>>(ei, S_id, out, E);
    new_edge_kernel<<<(nr + 255) / 256, 256>>>(row_new, col_new, pos, out, E, nr, N);
}

// round 2
// speedup vs baseline: 4.6127x; 4.6127x over previous
#include <cuda_runtime.h>
#include <math.h>
#include <stdint.h>

// ---------------------------------------------------------------------------
// ProteinFeatures: per-edge features
//   E row (39) = [cos(8), sin(8), RBF(16), dU(3), Q(4)]
// Outputs concatenated as float32:
//   [ E (Eg*39) | edge_index (2*Eg) | edge_length (Eg) |
//     new_edge_index (2*nr) | E_new (nr*39) ]
// ---------------------------------------------------------------------------

#define NMAX 210000
#define EPB 256   // edges per block (== blockDim.x)

__device__ float g_Xca[NMAX * 3];
__device__ float g_O[NMAX * 9];

__device__ __forceinline__ float3 f3sub(float3 a, float3 b) {
    return make_float3(a.x - b.x, a.y - b.y, a.z - b.z);
}
__device__ __forceinline__ float3 f3cross(float3 a, float3 b) {
    return make_float3(a.y * b.z - a.z * b.y,
                       a.z * b.x - a.x * b.z,
                       a.x * b.y - a.y * b.x);
}
__device__ __forceinline__ float f3dot(float3 a, float3 b) {
    return a.x * b.x + a.y * b.y + a.z * b.z;
}
__device__ __forceinline__ float3 f3norm(float3 a) {
    float n = sqrtf(f3dot(a, a));
    float inv = 1.0f / fmaxf(n, 1e-12f);
    return make_float3(a.x * inv, a.y * inv, a.z * inv);
}
__device__ __forceinline__ float fsgn(float v) {
    return (float)((v > 0.0f) - (v < 0.0f));
}

// freq_k = 10000^(-2k/16) = 10^(-k/2)
__constant__ float c_freq[8] = {
    1.0f, 0.31622776601683794f, 0.1f, 0.03162277660168379f,
    0.01f, 0.0031622776601683794f, 0.001f, 0.00031622776601683794f
};

// ---------------------------------------------------------------------------
// Kernel 1: contiguous X_ca and per-node orientation frames O[i]
// ---------------------------------------------------------------------------
__global__ void prep_kernel(const float* __restrict__ X, int N) {
    int i = blockIdx.x * blockDim.x + threadIdx.x;
    if (i >= N) return;

    float3 xc = make_float3(X[i * 12 + 3], X[i * 12 + 4], X[i * 12 + 5]);
    g_Xca[i * 3 + 0] = xc.x;
    g_Xca[i * 3 + 1] = xc.y;
    g_Xca[i * 3 + 2] = xc.z;

    float* Orow = g_O + (size_t)i * 9;
    if (i == 0 || i == N - 1) {
#pragma unroll
        for (int j = 0; j < 9; j++) Orow[j] = 0.0f;
        return;
    }
    float3 xm = make_float3(X[(i - 1) * 12 + 3], X[(i - 1) * 12 + 4], X[(i - 1) * 12 + 5]);
    float3 xp = make_float3(X[(i + 1) * 12 + 3], X[(i + 1) * 12 + 4], X[(i + 1) * 12 + 5]);

    float3 u2 = f3norm(f3sub(xc, xm));   // U[i-1]
    float3 u1 = f3norm(f3sub(xp, xc));   // U[i]
    float3 n2 = f3norm(f3cross(u2, u1));
    float3 o1 = f3norm(f3sub(u2, u1));
    float3 r2 = f3cross(o1, n2);

    Orow[0] = o1.x; Orow[1] = o1.y; Orow[2] = o1.z;
    Orow[3] = n2.x; Orow[4] = n2.y; Orow[5] = n2.z;
    Orow[6] = r2.x; Orow[7] = r2.y; Orow[8] = r2.z;
}

// ---------------------------------------------------------------------------
// Kernel 2: per-edge features, smem-staged coalesced row output
// ---------------------------------------------------------------------------
__global__ __launch_bounds__(EPB)
void edge_kernel(const int* __restrict__ ei,
                 const int* __restrict__ S_id,
                 float* __restrict__ out,
                 int E) {
    __shared__ __align__(16) float s[EPB * 39];

    int e0 = blockIdx.x * EPB;
    int e  = e0 + threadIdx.x;

    if (e < E) {
        int r = ei[e];
        int c = ei[E + e];

        float3 xr = make_float3(g_Xca[r * 3 + 0], g_Xca[r * 3 + 1], g_Xca[r * 3 + 2]);
        float3 xc = make_float3(g_Xca[c * 3 + 0], g_Xca[c * 3 + 1], g_Xca[c * 3 + 2]);

        float3 dXe = f3sub(xc, xr);
        float d = sqrtf(f3dot(dXe, dXe));

        float* Erow = s + threadIdx.x * 39;   // stride 39 (odd) -> conflict-free

        // positional encodings: cols 0..7 cos, 8..15 sin
        float eidx = (float)(S_id[c] - S_id[r]);
#pragma unroll
        for (int k = 0; k < 8; k++) {
            float a = eidx * c_freq[k];
            float sv, cv;
            sincosf(a, &sv, &cv);
            Erow[k]     = cv;
            Erow[8 + k] = sv;
        }

        // RBF: cols 16..31
#pragma unroll
        for (int j = 0; j < 16; j++) {
            float t = (d - (float)j * (20.0f / 15.0f)) * 0.8f;
            Erow[16 + j] = expf(-t * t);
        }

        // orientation features
        float Or[9], Oc[9];
        const float* po = g_O + (size_t)r * 9;
        const float* pc = g_O + (size_t)c * 9;
#pragma unroll
        for (int j = 0; j < 9; j++) { Or[j] = po[j]; Oc[j] = pc[j]; }

        // dU = l2norm(O[c] @ dXe)
        float du0 = Oc[0] * dXe.x + Oc[1] * dXe.y + Oc[2] * dXe.z;
        float du1 = Oc[3] * dXe.x + Oc[4] * dXe.y + Oc[5] * dXe.z;
        float du2 = Oc[6] * dXe.x + Oc[7] * dXe.y + Oc[8] * dXe.z;
        {
            float n = sqrtf(du0 * du0 + du1 * du1 + du2 * du2);
            float inv = 1.0f / fmaxf(n, 1e-12f);
            Erow[32] = du0 * inv; Erow[33] = du1 * inv; Erow[34] = du2 * inv;
        }

        // R = O[r] @ O[c]^T
        float R[3][3];
#pragma unroll
        for (int i = 0; i < 3; i++) {
#pragma unroll
            for (int k = 0; k < 3; k++) {
                R[i][k] = Or[3 * i + 0] * Oc[3 * k + 0]
                        + Or[3 * i + 1] * Oc[3 * k + 1]
                        + Or[3 * i + 2] * Oc[3 * k + 2];
            }
        }

        float Rxx = R[0][0], Ryy = R[1][1], Rzz = R[2][2];
        float m0 = 0.5f * sqrtf(fabsf(1.0f + Rxx - Ryy - Rzz));
        float m1 = 0.5f * sqrtf(fabsf(1.0f - Rxx + Ryy - Rzz));
        float m2 = 0.5f * sqrtf(fabsf(1.0f - Rxx - Ryy + Rzz));
        float qx = fsgn(R[2][1] - R[1][2]) * m0;
        float qy = fsgn(R[0][2] - R[2][0]) * m1;
        float qz = fsgn(R[1][0] - R[0][1]) * m2;
        float qw = 0.5f * sqrtf(fmaxf(1.0f + Rxx + Ryy + Rzz, 0.0f));
        {
            float n = sqrtf(qx * qx + qy * qy + qz * qz + qw * qw);
            float inv = 1.0f / fmaxf(n, 1e-12f);
            Erow[35] = qx * inv; Erow[36] = qy * inv; Erow[37] = qz * inv; Erow[38] = qw * inv;
        }

        // edge_index passthrough and edge_length (already coalesced)
        size_t offEI = (size_t)39 * E;
        size_t offEL = (size_t)41 * E;
        out[offEI + e]     = (float)r;
        out[offEI + E + e] = (float)c;
        out[offEL + e]     = d;
    }

    __syncthreads();

    // Coalesced block copy: smem -> out[e0*39 .. e0*39 + count*39)
    int count = min(EPB, E - e0);
    float* dst = out + (size_t)e0 * 39;
    if (count == EPB) {
        // 256*39*4 = 39936 B block region, 128B-aligned; vectorize
        float4* dst4 = reinterpret_cast<float4*>(dst);
        const float4* s4 = reinterpret_cast<const float4*>(s);
#pragma unroll
        for (int i = threadIdx.x; i < (EPB * 39) / 4; i += EPB)
            dst4[i] = s4[i];
    } else {
        int total = count * 39;
        for (int i = threadIdx.x; i < total; i += EPB)
            dst[i] = s[i];
    }
}

// ---------------------------------------------------------------------------
// Kernel 3: new (ligand) edges, smem-staged coalesced output
// ---------------------------------------------------------------------------
__global__ __launch_bounds__(EPB)
void new_edge_kernel(const int* __restrict__ row_new,
                     const int* __restrict__ col_new,
                     const float* __restrict__ pos,
                     float* __restrict__ out,
                     int E, int nr, int N) {
    __shared__ __align__(16) float s[EPB * 39];

    int t0 = blockIdx.x * EPB;
    int t  = t0 + threadIdx.x;

    size_t offNEI = (size_t)42 * E;
    size_t offEN  = offNEI + (size_t)2 * nr;

    if (t < nr) {
        int rn = row_new[t];
        int cn = col_new[t];

        float dx = g_Xca[rn * 3 + 0] - pos[cn * 3 + 0];
        float dy = g_Xca[rn * 3 + 1] - pos[cn * 3 + 1];
        float dz = g_Xca[rn * 3 + 2] - pos[cn * 3 + 2];
        float d = sqrtf(dx * dx + dy * dy + dz * dz);

        out[offNEI + t]      = (float)rn;
        out[offNEI + nr + t] = (float)(cn + N);

        float* Erow = s + threadIdx.x * 39;
#pragma unroll
        for (int k = 0; k < 16; k++) Erow[k] = 0.0f;
#pragma unroll
        for (int j = 0; j < 16; j++) {
            float u = (d - (float)j * (20.0f / 15.0f)) * 0.8f;
            Erow[16 + j] = expf(-u * u);
        }
#pragma unroll
        for (int k = 32; k < 39; k++) Erow[k] = 0.0f;
    }

    __syncthreads();

    int count = min(EPB, nr - t0);
    if (count <= 0) return;
    float* dst = out + offEN + (size_t)t0 * 39;
    int total = count * 39;
    for (int i = threadIdx.x; i < total; i += EPB)
        dst[i] = s[i];
}

// ---------------------------------------------------------------------------
extern "C" void kernel_launch(void* const* d_in, const int* in_sizes, int n_in,
                              void* d_out, int out_size) {
    const float* X       = (const float*)d_in[0];
    const float* pos     = (const float*)d_in[1];
    const int*   ei      = (const int*)d_in[2];
    const int*   S_id    = (const int*)d_in[3];
    // d_in[4] = batch (unused: col_new already holds batch[row_new])
    const int*   row_new = (const int*)d_in[5];
    const int*   col_new = (const int*)d_in[6];

    int N  = in_sizes[0] / 12;
    int E  = in_sizes[2] / 2;
    int nr = in_sizes[5];

    float* out = (float*)d_out;

    prep_kernel<<<(N + 255) / 256, 256>>>(X, N);
    edge_kernel<<<(E + EPB - 1) / EPB, EPB>>>(ei, S_id, out, E);
    new_edge_kernel<<<(nr + EPB - 1) / EPB, EPB>>>(row_new, col_new, pos, out, E, nr, N);
}

// round 3
// speedup vs baseline: 5.2907x; 1.1470x over previous
#include <cuda_runtime.h>
#include <math.h>
#include <stdint.h>

// ---------------------------------------------------------------------------
// ProteinFeatures, fused:
//   kernel 1 (prep): per-node record = [o1 | n2 | r2 | X_ca] packed as 3 float4
//   kernel 2 (fused): edge blocks + new-edge tail blocks
// Output float32 layout:
//   [ E (Eg*39) | edge_index (2*Eg) | edge_length (Eg) |
//     new_edge_index (2*nr) | E_new (nr*39) ]
// ---------------------------------------------------------------------------

#define NMAX 210000
#define EPB 256

// rec[i*3+0] = (o1.x, o1.y, o1.z, n2.x)
// rec[i*3+1] = (n2.y, n2.z, r2.x, r2.y)
// rec[i*3+2] = (r2.z, x,    y,    z   )
__device__ __align__(16) float4 g_rec[NMAX * 3];

__device__ __forceinline__ float3 f3sub(float3 a, float3 b) {
    return make_float3(a.x - b.x, a.y - b.y, a.z - b.z);
}
__device__ __forceinline__ float3 f3cross(float3 a, float3 b) {
    return make_float3(a.y * b.z - a.z * b.y,
                       a.z * b.x - a.x * b.z,
                       a.x * b.y - a.y * b.x);
}
__device__ __forceinline__ float f3dot(float3 a, float3 b) {
    return a.x * b.x + a.y * b.y + a.z * b.z;
}
__device__ __forceinline__ float3 f3norm(float3 a) {
    float n = sqrtf(f3dot(a, a));
    float inv = 1.0f / fmaxf(n, 1e-12f);
    return make_float3(a.x * inv, a.y * inv, a.z * inv);
}
__device__ __forceinline__ float fsgn(float v) {
    return (float)((v > 0.0f) - (v < 0.0f));
}

// freq_k = 10000^(-2k/16) = 10^(-k/2)
__constant__ float c_freq[8] = {
    1.0f, 0.31622776601683794f, 0.1f, 0.03162277660168379f,
    0.01f, 0.0031622776601683794f, 0.001f, 0.00031622776601683794f
};

// ---------------------------------------------------------------------------
// Kernel 1: build packed per-node records
// ---------------------------------------------------------------------------
__global__ void prep_kernel(const float* __restrict__ X, int N) {
    int i = blockIdx.x * blockDim.x + threadIdx.x;
    if (i >= N) return;

    float3 xc = make_float3(X[i * 12 + 3], X[i * 12 + 4], X[i * 12 + 5]);

    float3 o1 = make_float3(0.f, 0.f, 0.f);
    float3 n2 = o1, r2 = o1;
    if (i > 0 && i < N - 1) {
        float3 xm = make_float3(X[(i - 1) * 12 + 3], X[(i - 1) * 12 + 4], X[(i - 1) * 12 + 5]);
        float3 xp = make_float3(X[(i + 1) * 12 + 3], X[(i + 1) * 12 + 4], X[(i + 1) * 12 + 5]);
        float3 u2 = f3norm(f3sub(xc, xm));
        float3 u1 = f3norm(f3sub(xp, xc));
        n2 = f3norm(f3cross(u2, u1));
        o1 = f3norm(f3sub(u2, u1));
        r2 = f3cross(o1, n2);
    }

    g_rec[i * 3 + 0] = make_float4(o1.x, o1.y, o1.z, n2.x);
    g_rec[i * 3 + 1] = make_float4(n2.y, n2.z, r2.x, r2.y);
    g_rec[i * 3 + 2] = make_float4(r2.z, xc.x, xc.y, xc.z);
}

// ---------------------------------------------------------------------------
// Kernel 2: fused edge + new-edge
// ---------------------------------------------------------------------------
__global__ __launch_bounds__(EPB)
void fused_kernel(const int* __restrict__ ei,
                  const int* __restrict__ S_id,
                  const int* __restrict__ row_new,
                  const int* __restrict__ col_new,
                  const float* __restrict__ pos,
                  float* __restrict__ out,
                  int E, int nr, int N, int eblocks) {
    __shared__ __align__(16) float s[EPB * 39];

    if ((int)blockIdx.x < eblocks) {
        // ---------------- edge path ----------------
        int e0 = blockIdx.x * EPB;
        int e  = e0 + threadIdx.x;

        if (e < E) {
            int r = ei[e];
            int c = ei[E + e];

            float4 a0 = g_rec[r * 3 + 0];
            float4 a1 = g_rec[r * 3 + 1];
            float4 a2 = g_rec[r * 3 + 2];
            float4 b0 = g_rec[c * 3 + 0];
            float4 b1 = g_rec[c * 3 + 1];
            float4 b2 = g_rec[c * 3 + 2];

            float Or[9] = {a0.x, a0.y, a0.z, a0.w, a1.x, a1.y, a1.z, a1.w, a2.x};
            float Oc[9] = {b0.x, b0.y, b0.z, b0.w, b1.x, b1.y, b1.z, b1.w, b2.x};
            float3 xr = make_float3(a2.y, a2.z, a2.w);
            float3 xc = make_float3(b2.y, b2.z, b2.w);

            float3 dXe = f3sub(xc, xr);
            float d = sqrtf(f3dot(dXe, dXe));

            float* Erow = s + threadIdx.x * 39;   // stride 39 (odd) -> conflict-free

            float eidx = (float)(S_id[c] - S_id[r]);
#pragma unroll
            for (int k = 0; k < 8; k++) {
                float sv, cv;
                sincosf(eidx * c_freq[k], &sv, &cv);
                Erow[k]     = cv;
                Erow[8 + k] = sv;
            }

#pragma unroll
            for (int j = 0; j < 16; j++) {
                float t = (d - (float)j * (20.0f / 15.0f)) * 0.8f;
                Erow[16 + j] = expf(-t * t);
            }

            // dU = l2norm(O[c] @ dXe)
            float du0 = Oc[0] * dXe.x + Oc[1] * dXe.y + Oc[2] * dXe.z;
            float du1 = Oc[3] * dXe.x + Oc[4] * dXe.y + Oc[5] * dXe.z;
            float du2 = Oc[6] * dXe.x + Oc[7] * dXe.y + Oc[8] * dXe.z;
            {
                float n = sqrtf(du0 * du0 + du1 * du1 + du2 * du2);
                float inv = 1.0f / fmaxf(n, 1e-12f);
                Erow[32] = du0 * inv; Erow[33] = du1 * inv; Erow[34] = du2 * inv;
            }

            // R = O[r] @ O[c]^T
            float R[3][3];
#pragma unroll
            for (int i = 0; i < 3; i++)
#pragma unroll
                for (int k = 0; k < 3; k++)
                    R[i][k] = Or[3 * i + 0] * Oc[3 * k + 0]
                            + Or[3 * i + 1] * Oc[3 * k + 1]
                            + Or[3 * i + 2] * Oc[3 * k + 2];

            float Rxx = R[0][0], Ryy = R[1][1], Rzz = R[2][2];
            float m0 = 0.5f * sqrtf(fabsf(1.0f + Rxx - Ryy - Rzz));
            float m1 = 0.5f * sqrtf(fabsf(1.0f - Rxx + Ryy - Rzz));
            float m2 = 0.5f * sqrtf(fabsf(1.0f - Rxx - Ryy + Rzz));
            float qx = fsgn(R[2][1] - R[1][2]) * m0;
            float qy = fsgn(R[0][2] - R[2][0]) * m1;
            float qz = fsgn(R[1][0] - R[0][1]) * m2;
            float qw = 0.5f * sqrtf(fmaxf(1.0f + Rxx + Ryy + Rzz, 0.0f));
            {
                float n = sqrtf(qx * qx + qy * qy + qz * qz + qw * qw);
                float inv = 1.0f / fmaxf(n, 1e-12f);
                Erow[35] = qx * inv; Erow[36] = qy * inv; Erow[37] = qz * inv; Erow[38] = qw * inv;
            }

            size_t offEI = (size_t)39 * E;
            size_t offEL = (size_t)41 * E;
            out[offEI + e]     = (float)r;
            out[offEI + E + e] = (float)c;
            out[offEL + e]     = d;
        }

        __syncthreads();

        int count = min(EPB, E - e0);
        float* dst = out + (size_t)e0 * 39;
        if (count == EPB) {
            float4* dst4 = reinterpret_cast<float4*>(dst);
            const float4* s4 = reinterpret_cast<const float4*>(s);
#pragma unroll
            for (int i = threadIdx.x; i < (EPB * 39) / 4; i += EPB)
                dst4[i] = s4[i];
        } else {
            int total = count * 39;
            for (int i = threadIdx.x; i < total; i += EPB)
                dst[i] = s[i];
        }
    } else {
        // ---------------- new-edge path ----------------
        int t0 = (blockIdx.x - eblocks) * EPB;
        int t  = t0 + threadIdx.x;

        size_t offNEI = (size_t)42 * E;
        size_t offEN  = offNEI + (size_t)2 * nr;

        if (t < nr) {
            int rn = row_new[t];
            int cn = col_new[t];

            float4 r2rec = g_rec[rn * 3 + 2];
            float dx = r2rec.y - pos[cn * 3 + 0];
            float dy = r2rec.z - pos[cn * 3 + 1];
            float dz = r2rec.w - pos[cn * 3 + 2];
            float d = sqrtf(dx * dx + dy * dy + dz * dz);

            out[offNEI + t]      = (float)rn;
            out[offNEI + nr + t] = (float)(cn + N);

            float* Erow = s + threadIdx.x * 39;
#pragma unroll
            for (int k = 0; k < 16; k++) Erow[k] = 0.0f;
#pragma unroll
            for (int j = 0; j < 16; j++) {
                float u = (d - (float)j * (20.0f / 15.0f)) * 0.8f;
                Erow[16 + j] = expf(-u * u);
            }
#pragma unroll
            for (int k = 32; k < 39; k++) Erow[k] = 0.0f;
        }

        __syncthreads();

        int count = min(EPB, nr - t0);
        if (count <= 0) return;
        float* dst = out + offEN + (size_t)t0 * 39;
        int total = count * 39;
        for (int i = threadIdx.x; i < total; i += EPB)
            dst[i] = s[i];
    }
}

// ---------------------------------------------------------------------------
extern "C" void kernel_launch(void* const* d_in, const int* in_sizes, int n_in,
                              void* d_out, int out_size) {
    const float* X       = (const float*)d_in[0];
    const float* pos     = (const float*)d_in[1];
    const int*   ei      = (const int*)d_in[2];
    const int*   S_id    = (const int*)d_in[3];
    // d_in[4] = batch (unused)
    const int*   row_new = (const int*)d_in[5];
    const int*   col_new = (const int*)d_in[6];

    int N  = in_sizes[0] / 12;
    int E  = in_sizes[2] / 2;
    int nr = in_sizes[5];

    float* out = (float*)d_out;

    int eblocks = (E + EPB - 1) / EPB;
    int nblocks = (nr + EPB - 1) / EPB;

    prep_kernel<<<(N + 255) / 256, 256>>>(X, N);
    fused_kernel<<<eblocks + nblocks, EPB>>>(ei, S_id, row_new, col_new, pos,
                                             out, E, nr, N, eblocks);
}